// round 1
// baseline (speedup 1.0000x reference)
#include <cuda_runtime.h>
#include <cstddef>

#define NB   16384
#define LSEQ 200
#define EMB  128
#define NCLS 1000

// Scratch for pooled embeddings (alloc-free rule: __device__ global).
__device__ float g_pooled[(size_t)NB * EMB];

// ---------------------------------------------------------------------------
// Stage 1: masked embedding-bag sum pool.
// One block per batch row; 128 threads = one per embedding dim.
// Tokens staged in shared; 4 independent accumulators for memory-level
// parallelism on the L2-resident gathers.
// ---------------------------------------------------------------------------
__global__ __launch_bounds__(128) void pool_kernel(const int* __restrict__ seq,
                                                   const float* __restrict__ table) {
    __shared__ int s_tok[LSEQ];
    const int b = blockIdx.x;
    const int* row = seq + (size_t)b * LSEQ;
    for (int i = threadIdx.x; i < LSEQ; i += 128) s_tok[i] = row[i];
    __syncthreads();

    const int e = threadIdx.x;
    float a0 = 0.f, a1 = 0.f, a2 = 0.f, a3 = 0.f;
    #pragma unroll 2
    for (int l = 0; l < LSEQ; l += 4) {   // LSEQ divisible by 4
        const int t0 = s_tok[l + 0];
        const int t1 = s_tok[l + 1];
        const int t2 = s_tok[l + 2];
        const int t3 = s_tok[l + 3];
        if (t0) a0 += __ldg(table + (size_t)t0 * EMB + e);
        if (t1) a1 += __ldg(table + (size_t)t1 * EMB + e);
        if (t2) a2 += __ldg(table + (size_t)t2 * EMB + e);
        if (t3) a3 += __ldg(table + (size_t)t3 * EMB + e);
    }
    g_pooled[(size_t)b * EMB + e] = (a0 + a1) + (a2 + a3);
}

// ---------------------------------------------------------------------------
// Stage 2: out[m,n] = sum_k pooled[m,k] * W[n,k] + bias[n]
// 64x64 output tile per block, BK=32, 256 threads, 4x4 register micro-tile.
// Shared tiles are k-major so the inner loop does two float4 LDS per thread.
// ---------------------------------------------------------------------------
#define BM  64
#define BN  64
#define BK  32
#define PAD 4

__global__ __launch_bounds__(256) void gemm_kernel(const float* __restrict__ W,
                                                   const float* __restrict__ bias,
                                                   float* __restrict__ out) {
    __shared__ float As[BK][BM + PAD];
    __shared__ float Bs[BK][BN + PAD];

    const int tid = threadIdx.x;
    const int tx  = tid & 15;   // n direction (16 threads)
    const int ty  = tid >> 4;   // m direction (16 threads)
    const int m0  = blockIdx.x * BM;
    const int n0  = blockIdx.y * BN;

    float acc[4][4] = {};

    for (int kk = 0; kk < EMB; kk += BK) {
        // Load A tile: BM x BK = 2048 floats = 512 float4, 2 per thread.
        #pragma unroll
        for (int i = 0; i < 2; ++i) {
            const int f = tid * 2 + i;
            const int m = f >> 3;           // 0..63
            const int k = (f & 7) << 2;     // 0,4,..,28
            const float4 v = *reinterpret_cast<const float4*>(
                g_pooled + (size_t)(m0 + m) * EMB + kk + k);
            As[k + 0][m] = v.x; As[k + 1][m] = v.y;
            As[k + 2][m] = v.z; As[k + 3][m] = v.w;
        }
        // Load B tile (fc_w is [NCLS][EMB] row-major, i.e. already n-by-k).
        #pragma unroll
        for (int i = 0; i < 2; ++i) {
            const int f  = tid * 2 + i;
            const int n  = f >> 3;
            const int k  = (f & 7) << 2;
            const int ng = n0 + n;
            float4 v = make_float4(0.f, 0.f, 0.f, 0.f);
            if (ng < NCLS)
                v = *reinterpret_cast<const float4*>(W + (size_t)ng * EMB + kk + k);
            Bs[k + 0][n] = v.x; Bs[k + 1][n] = v.y;
            Bs[k + 2][n] = v.z; Bs[k + 3][n] = v.w;
        }
        __syncthreads();

        #pragma unroll
        for (int k = 0; k < BK; ++k) {
            const float4 a = *reinterpret_cast<const float4*>(&As[k][ty * 4]);
            const float4 b = *reinterpret_cast<const float4*>(&Bs[k][tx * 4]);
            const float av[4] = {a.x, a.y, a.z, a.w};
            const float bv[4] = {b.x, b.y, b.z, b.w};
            #pragma unroll
            for (int i = 0; i < 4; ++i)
                #pragma unroll
                for (int j = 0; j < 4; ++j)
                    acc[i][j] += av[i] * bv[j];
        }
        __syncthreads();
    }

    // Epilogue: add bias, vectorized stores.
    // NCLS = 1000 is divisible by 4, and n is always a multiple of 4, so a
    // float4 store guarded by (n < NCLS) never crosses the boundary.
    #pragma unroll
    for (int i = 0; i < 4; ++i) {
        const int m = m0 + ty * 4 + i;
        const int n = n0 + tx * 4;
        if (n < NCLS) {
            float4 b4 = *reinterpret_cast<const float4*>(bias + n);
            float4 r;
            r.x = acc[i][0] + b4.x;
            r.y = acc[i][1] + b4.y;
            r.z = acc[i][2] + b4.z;
            r.w = acc[i][3] + b4.w;
            *reinterpret_cast<float4*>(out + (size_t)m * NCLS + n) = r;
        }
    }
}

extern "C" void kernel_launch(void* const* d_in, const int* in_sizes, int n_in,
                              void* d_out, int out_size) {
    const int*   seq   = (const int*)d_in[0];
    const float* table = (const float*)d_in[1];
    const float* W     = (const float*)d_in[2];
    const float* bias  = (const float*)d_in[3];
    float*       out   = (float*)d_out;

    pool_kernel<<<NB, 128>>>(seq, table);

    dim3 grid(NB / BM, (NCLS + BN - 1) / BN);
    gemm_kernel<<<grid, 256>>>(W, bias, out);
}

// round 2
// speedup vs baseline: 1.3292x; 1.3292x over previous
#include <cuda_runtime.h>
#include <cuda_fp16.h>
#include <cstddef>

#define VOCAB 100000
#define NB    16384
#define LSEQ  200
#define EMB   128
#define NCLS  1000

// Scratch (alloc-free rule: __device__ globals).
__device__ __half g_table_h[(size_t)VOCAB * EMB];   // 25.6 MB fp16 table
__device__ float  g_pooled[(size_t)NB * EMB];       // 8 MB pooled output

// ---------------------------------------------------------------------------
// Stage 0: convert embedding table fp32 -> fp16 (halves gather traffic).
// ---------------------------------------------------------------------------
__global__ __launch_bounds__(256) void convert_kernel(const float* __restrict__ t) {
    const size_t i = (size_t)blockIdx.x * 256 + threadIdx.x;   // one float4 each
    const float4 v = reinterpret_cast<const float4*>(t)[i];
    union { __half2 h[2]; uint2 u; } pk;
    pk.h[0] = __floats2half2_rn(v.x, v.y);
    pk.h[1] = __floats2half2_rn(v.z, v.w);
    reinterpret_cast<uint2*>(g_table_h)[i] = pk.u;
}

// ---------------------------------------------------------------------------
// Stage 1: masked embedding-bag sum pool (fp16 gathers, fp32 accumulate).
// One warp per batch row; lane owns 4 dims via half4 (uint2) loads.
// 4 independent accumulators for MLP.
// ---------------------------------------------------------------------------
__device__ __forceinline__ void hacc(float4& a, uint2 u) {
    const float2 f0 = __half22float2(*reinterpret_cast<__half2*>(&u.x));
    const float2 f1 = __half22float2(*reinterpret_cast<__half2*>(&u.y));
    a.x += f0.x; a.y += f0.y; a.z += f1.x; a.w += f1.y;
}

__global__ __launch_bounds__(256) void pool_kernel(const int* __restrict__ seq) {
    __shared__ int s_tok[8][LSEQ];
    const int wid  = threadIdx.x >> 5;
    const int lane = threadIdx.x & 31;
    const int b0   = blockIdx.x * 8;

    for (int i = threadIdx.x; i < 8 * LSEQ; i += 256)
        s_tok[i / LSEQ][i % LSEQ] = seq[(size_t)b0 * LSEQ + i];
    __syncthreads();

    float4 a0 = {0,0,0,0}, a1 = {0,0,0,0}, a2 = {0,0,0,0}, a3 = {0,0,0,0};

    #pragma unroll 2
    for (int l = 0; l < LSEQ; l += 4) {
        const int t0 = s_tok[wid][l + 0];
        const int t1 = s_tok[wid][l + 1];
        const int t2 = s_tok[wid][l + 2];
        const int t3 = s_tok[wid][l + 3];
        if (t0) hacc(a0, reinterpret_cast<const uint2*>(g_table_h + (size_t)t0 * EMB)[lane]);
        if (t1) hacc(a1, reinterpret_cast<const uint2*>(g_table_h + (size_t)t1 * EMB)[lane]);
        if (t2) hacc(a2, reinterpret_cast<const uint2*>(g_table_h + (size_t)t2 * EMB)[lane]);
        if (t3) hacc(a3, reinterpret_cast<const uint2*>(g_table_h + (size_t)t3 * EMB)[lane]);
    }

    float4 r;
    r.x = (a0.x + a1.x) + (a2.x + a3.x);
    r.y = (a0.y + a1.y) + (a2.y + a3.y);
    r.z = (a0.z + a1.z) + (a2.z + a3.z);
    r.w = (a0.w + a1.w) + (a2.w + a3.w);
    reinterpret_cast<float4*>(g_pooled + (size_t)(b0 + wid) * EMB)[lane] = r;
}

// ---------------------------------------------------------------------------
// Stage 2: out[m,n] = pooled[m,:] . W[n,:] + bias[n]
// Classic 128x128x8 SGEMM, 256 threads, 8x8 micro-tile (64 FFMA : 4 LDS.128).
// ---------------------------------------------------------------------------
__global__ __launch_bounds__(256) void gemm_kernel(const float* __restrict__ W,
                                                   const float* __restrict__ bias,
                                                   float* __restrict__ out) {
    __shared__ float As[8][128];
    __shared__ float Bs[8][128];

    const int tid = threadIdx.x;
    const int tx  = tid & 15;     // n
    const int ty  = tid >> 4;     // m
    const int m0  = blockIdx.x * 128;
    const int n0  = blockIdx.y * 128;

    const int lrow = tid >> 1;          // 0..127
    const int lk4  = (tid & 1) * 4;     // 0 or 4

    float acc[8][8] = {};

    for (int kk = 0; kk < EMB; kk += 8) {
        const float4 av = *reinterpret_cast<const float4*>(
            g_pooled + (size_t)(m0 + lrow) * EMB + kk + lk4);
        float4 bv = make_float4(0.f, 0.f, 0.f, 0.f);
        if (n0 + lrow < NCLS)
            bv = *reinterpret_cast<const float4*>(W + (size_t)(n0 + lrow) * EMB + kk + lk4);

        __syncthreads();
        As[lk4 + 0][lrow] = av.x; As[lk4 + 1][lrow] = av.y;
        As[lk4 + 2][lrow] = av.z; As[lk4 + 3][lrow] = av.w;
        Bs[lk4 + 0][lrow] = bv.x; Bs[lk4 + 1][lrow] = bv.y;
        Bs[lk4 + 2][lrow] = bv.z; Bs[lk4 + 3][lrow] = bv.w;
        __syncthreads();

        #pragma unroll
        for (int k = 0; k < 8; ++k) {
            float af[8], bf[8];
            const float4 aL = *reinterpret_cast<const float4*>(&As[k][ty * 4]);
            const float4 aH = *reinterpret_cast<const float4*>(&As[k][64 + ty * 4]);
            const float4 bL = *reinterpret_cast<const float4*>(&Bs[k][tx * 4]);
            const float4 bH = *reinterpret_cast<const float4*>(&Bs[k][64 + tx * 4]);
            af[0]=aL.x; af[1]=aL.y; af[2]=aL.z; af[3]=aL.w;
            af[4]=aH.x; af[5]=aH.y; af[6]=aH.z; af[7]=aH.w;
            bf[0]=bL.x; bf[1]=bL.y; bf[2]=bL.z; bf[3]=bL.w;
            bf[4]=bH.x; bf[5]=bH.y; bf[6]=bH.z; bf[7]=bH.w;
            #pragma unroll
            for (int i = 0; i < 8; ++i)
                #pragma unroll
                for (int j = 0; j < 8; ++j)
                    acc[i][j] += af[i] * bf[j];
        }
    }

    // Epilogue: 2x2 grid of 4x4 sub-tiles, fused bias, float4 stores.
    #pragma unroll
    for (int im = 0; im < 2; ++im) {
        #pragma unroll
        for (int i = 0; i < 4; ++i) {
            const int m = m0 + im * 64 + ty * 4 + i;
            #pragma unroll
            for (int jn = 0; jn < 2; ++jn) {
                const int n = n0 + jn * 64 + tx * 4;
                if (n < NCLS) {   // n % 4 == 0 and NCLS % 4 == 0: safe float4
                    const float4 b4 = *reinterpret_cast<const float4*>(bias + n);
                    float4 r;
                    r.x = acc[im * 4 + i][jn * 4 + 0] + b4.x;
                    r.y = acc[im * 4 + i][jn * 4 + 1] + b4.y;
                    r.z = acc[im * 4 + i][jn * 4 + 2] + b4.z;
                    r.w = acc[im * 4 + i][jn * 4 + 3] + b4.w;
                    *reinterpret_cast<float4*>(out + (size_t)m * NCLS + n) = r;
                }
            }
        }
    }
}

extern "C" void kernel_launch(void* const* d_in, const int* in_sizes, int n_in,
                              void* d_out, int out_size) {
    const int*   seq   = (const int*)d_in[0];
    const float* table = (const float*)d_in[1];
    const float* W     = (const float*)d_in[2];
    const float* bias  = (const float*)d_in[3];
    float*       out   = (float*)d_out;

    convert_kernel<<<(VOCAB * EMB / 4 + 255) / 256, 256>>>(table);
    pool_kernel<<<NB / 8, 256>>>(seq);

    dim3 grid(NB / 128, (NCLS + 127) / 128);
    gemm_kernel<<<grid, 256>>>(W, bias, out);
}

// round 3
// speedup vs baseline: 2.3786x; 1.7895x over previous
#include <cuda_runtime.h>
#include <cuda_fp16.h>
#include <cstddef>
#include <cstdint>

#define VOCAB 100000
#define NB    16384
#define LSEQ  200
#define EMB   128
#define NCLS  1000

// Scratch (alloc-free rule: __device__ globals).
__device__ __half g_table_h[(size_t)VOCAB * EMB];   // 25.6 MB fp16 table
__device__ __half g_w_h[(size_t)NCLS * EMB];        // 256 KB fp16 weights
__device__ __half g_pooled_h[(size_t)NB * EMB];     // 4 MB pooled (fp16)

// ---------------------------------------------------------------------------
// Stage 0: convert table AND fc_w fp32 -> fp16 in one launch.
// ---------------------------------------------------------------------------
#define N_TBL4 ((size_t)VOCAB * EMB / 4)   // 3,200,000 float4
#define N_W4   ((size_t)NCLS * EMB / 4)    //    32,000 float4

__global__ __launch_bounds__(256) void convert_kernel(const float* __restrict__ t,
                                                      const float* __restrict__ W) {
    const size_t i = (size_t)blockIdx.x * 256 + threadIdx.x;
    float4 v;
    if (i < N_TBL4) {
        v = reinterpret_cast<const float4*>(t)[i];
    } else if (i < N_TBL4 + N_W4) {
        v = reinterpret_cast<const float4*>(W)[i - N_TBL4];
    } else {
        return;
    }
    union { __half2 h[2]; uint2 u; } pk;
    pk.h[0] = __floats2half2_rn(v.x, v.y);
    pk.h[1] = __floats2half2_rn(v.z, v.w);
    if (i < N_TBL4) reinterpret_cast<uint2*>(g_table_h)[i] = pk.u;
    else            reinterpret_cast<uint2*>(g_w_h)[i - N_TBL4] = pk.u;
}

// ---------------------------------------------------------------------------
// Stage 1: masked embedding-bag sum pool (fp16 gathers, fp32 acc, fp16 out).
// One warp per batch row; lane owns 4 dims (uint2 = half4 loads).
// ---------------------------------------------------------------------------
__device__ __forceinline__ void hacc(float4& a, uint2 u) {
    const float2 f0 = __half22float2(*reinterpret_cast<__half2*>(&u.x));
    const float2 f1 = __half22float2(*reinterpret_cast<__half2*>(&u.y));
    a.x += f0.x; a.y += f0.y; a.z += f1.x; a.w += f1.y;
}

__global__ __launch_bounds__(256) void pool_kernel(const int* __restrict__ seq) {
    __shared__ int s_tok[8][LSEQ];
    const int wid  = threadIdx.x >> 5;
    const int lane = threadIdx.x & 31;
    const int b0   = blockIdx.x * 8;

    for (int i = threadIdx.x; i < 8 * LSEQ; i += 256)
        s_tok[i / LSEQ][i % LSEQ] = seq[(size_t)b0 * LSEQ + i];
    __syncthreads();

    float4 a0 = {0,0,0,0}, a1 = {0,0,0,0}, a2 = {0,0,0,0}, a3 = {0,0,0,0};

    #pragma unroll 2
    for (int l = 0; l < LSEQ; l += 4) {
        const int t0 = s_tok[wid][l + 0];
        const int t1 = s_tok[wid][l + 1];
        const int t2 = s_tok[wid][l + 2];
        const int t3 = s_tok[wid][l + 3];
        if (t0) hacc(a0, reinterpret_cast<const uint2*>(g_table_h + (size_t)t0 * EMB)[lane]);
        if (t1) hacc(a1, reinterpret_cast<const uint2*>(g_table_h + (size_t)t1 * EMB)[lane]);
        if (t2) hacc(a2, reinterpret_cast<const uint2*>(g_table_h + (size_t)t2 * EMB)[lane]);
        if (t3) hacc(a3, reinterpret_cast<const uint2*>(g_table_h + (size_t)t3 * EMB)[lane]);
    }

    union { __half2 h[2]; uint2 u; } pk;
    pk.h[0] = __floats2half2_rn((a0.x + a1.x) + (a2.x + a3.x),
                                (a0.y + a1.y) + (a2.y + a3.y));
    pk.h[1] = __floats2half2_rn((a0.z + a1.z) + (a2.z + a3.z),
                                (a0.w + a1.w) + (a2.w + a3.w));
    reinterpret_cast<uint2*>(g_pooled_h + (size_t)(b0 + wid) * EMB)[lane] = pk.u;
}

// ---------------------------------------------------------------------------
// Stage 2: HMMA GEMM. out[m,n] = pooled[m,:] . W[n,:] + bias[n]
// Block tile 128(m) x 64(n), K=128 fully resident in smem (48 KB, XOR swizzle).
// 8 warps as 4(m) x 2(n); warp tile 32x32 via 2x4 mma.m16n8k16, 8 k-steps.
// ---------------------------------------------------------------------------
__device__ __forceinline__ void mma16816(float* d,
                                         uint32_t a0, uint32_t a1, uint32_t a2, uint32_t a3,
                                         uint32_t b0, uint32_t b1) {
    asm volatile(
        "mma.sync.aligned.m16n8k16.row.col.f32.f16.f16.f32 "
        "{%0,%1,%2,%3}, {%4,%5,%6,%7}, {%8,%9}, {%0,%1,%2,%3};\n"
        : "+f"(d[0]), "+f"(d[1]), "+f"(d[2]), "+f"(d[3])
        : "r"(a0), "r"(a1), "r"(a2), "r"(a3), "r"(b0), "r"(b1));
}

// smem half-index with 16B-chunk XOR swizzle: row has 16 chunks of 8 halfs;
// data chunk c of row r lives at chunk (c ^ (r&7)).
__device__ __forceinline__ int swz(int row, int chunk) {
    return row * 128 + ((chunk ^ (row & 7)) << 3);
}

__global__ __launch_bounds__(256) void gemm_kernel(const float* __restrict__ bias,
                                                   float* __restrict__ out) {
    __shared__ __half sA[128 * 128];   // 32 KB
    __shared__ __half sB[64 * 128];    // 16 KB  (total 48 KB exactly)

    const int tid  = threadIdx.x;
    const int lane = tid & 31;
    const int wid  = tid >> 5;
    const int wm   = wid & 3;          // 0..3 (m)
    const int wn   = wid >> 2;         // 0..1 (n)
    const int m0   = blockIdx.x * 128;
    const int n0   = blockIdx.y * 64;

    // --- load A tile: 128 rows x 16 chunks(16B), fully coalesced ---
    {
        const int r0 = tid >> 4;          // 0..15
        const int c  = tid & 15;          // chunk
        #pragma unroll
        for (int it = 0; it < 8; ++it) {
            const int r = r0 + it * 16;
            const uint4 v = reinterpret_cast<const uint4*>(
                g_pooled_h + (size_t)(m0 + r) * EMB)[c];
            *reinterpret_cast<uint4*>(&sA[swz(r, c)]) = v;
        }
    }
    // --- load B tile: 64 rows x 16 chunks, rows >= NCLS zero-filled ---
    {
        const int r0 = tid >> 4;
        const int c  = tid & 15;
        #pragma unroll
        for (int it = 0; it < 4; ++it) {
            const int r = r0 + it * 16;
            uint4 v = make_uint4(0u, 0u, 0u, 0u);
            if (n0 + r < NCLS)
                v = reinterpret_cast<const uint4*>(g_w_h + (size_t)(n0 + r) * EMB)[c];
            *reinterpret_cast<uint4*>(&sB[swz(r, c)]) = v;
        }
    }
    __syncthreads();

    float acc[2][4][4] = {};
    const int lq = lane >> 2;   // 0..7
    const int lr = lane & 3;    // 0..3

    #pragma unroll
    for (int ks = 0; ks < 8; ++ks) {
        uint32_t a[2][4];
        #pragma unroll
        for (int mt = 0; mt < 2; ++mt) {
            const int r   = wm * 32 + mt * 16 + lq;
            const int o0  = ((2 * ks)     ^ (r & 7)) * 8 + lr * 2;
            const int o1  = ((2 * ks + 1) ^ (r & 7)) * 8 + lr * 2;
            a[mt][0] = *reinterpret_cast<const uint32_t*>(&sA[r * 128 + o0]);
            a[mt][1] = *reinterpret_cast<const uint32_t*>(&sA[(r + 8) * 128 + o0]);
            a[mt][2] = *reinterpret_cast<const uint32_t*>(&sA[r * 128 + o1]);
            a[mt][3] = *reinterpret_cast<const uint32_t*>(&sA[(r + 8) * 128 + o1]);
        }
        #pragma unroll
        for (int nt = 0; nt < 4; ++nt) {
            const int n  = wn * 32 + nt * 8 + lq;
            const int o0 = ((2 * ks)     ^ (n & 7)) * 8 + lr * 2;
            const int o1 = ((2 * ks + 1) ^ (n & 7)) * 8 + lr * 2;
            const uint32_t b0 = *reinterpret_cast<const uint32_t*>(&sB[n * 128 + o0]);
            const uint32_t b1 = *reinterpret_cast<const uint32_t*>(&sB[n * 128 + o1]);
            #pragma unroll
            for (int mt = 0; mt < 2; ++mt)
                mma16816(acc[mt][nt], a[mt][0], a[mt][1], a[mt][2], a[mt][3], b0, b1);
        }
    }

    // --- epilogue: fused bias, predicated float2 stores ---
    #pragma unroll
    for (int nt = 0; nt < 4; ++nt) {
        const int n = n0 + wn * 32 + nt * 8 + lr * 2;   // even
        if (n < NCLS) {
            const float2 b2 = *reinterpret_cast<const float2*>(bias + n);
            #pragma unroll
            for (int mt = 0; mt < 2; ++mt) {
                const int m = m0 + wm * 32 + mt * 16 + lq;
                float2 r0, r1;
                r0.x = acc[mt][nt][0] + b2.x;
                r0.y = acc[mt][nt][1] + b2.y;
                r1.x = acc[mt][nt][2] + b2.x;
                r1.y = acc[mt][nt][3] + b2.y;
                *reinterpret_cast<float2*>(out + (size_t)m * NCLS + n)       = r0;
                *reinterpret_cast<float2*>(out + (size_t)(m + 8) * NCLS + n) = r1;
            }
        }
    }
}

extern "C" void kernel_launch(void* const* d_in, const int* in_sizes, int n_in,
                              void* d_out, int out_size) {
    const int*   seq   = (const int*)d_in[0];
    const float* table = (const float*)d_in[1];
    const float* W     = (const float*)d_in[2];
    const float* bias  = (const float*)d_in[3];
    float*       out   = (float*)d_out;

    const int conv_blocks = (int)((N_TBL4 + N_W4 + 255) / 256);
    convert_kernel<<<conv_blocks, 256>>>(table, W);

    pool_kernel<<<NB / 8, 256>>>(seq);

    dim3 grid(NB / 128, (NCLS + 63) / 64);
    gemm_kernel<<<grid, 256>>>(bias, out);
}